// round 7
// baseline (speedup 1.0000x reference)
#include <cuda_runtime.h>
#include <cuda_fp16.h>
#include <cstdint>
#include <math.h>

// ---------------------------------------------------------------------------
// Dropless MoE: N=4096, K=2, E=8, D=H=1024, fp32 in/out.
// GEMMs via mma.sync.m16n8k16 fp16 (fp32 accum), 512-thread CTAs,
// 128x128 / 128x256 tiles, 3-stage cp.async pipeline (1 barrier/chunk).
// Weight conversion overlapped on a forked stream (graph-capturable).
// ---------------------------------------------------------------------------

#define N_TOK   4096
#define TOPK    2
#define NEXP    8
#define DM      1024
#define DH      1024
#define NK      (N_TOK * TOPK)            // 8192
#define RTILE   128
#define MAXROWS (NK + NEXP * RTILE)       // 9216
#define NTILES  (MAXROWS / RTILE)         // 72
#define WELEMS  (NEXP * DM * DH)          // 8388608
#define KC      64                        // K-chunk (4 x k16 MMA steps)
#define NCHUNK  (DM / KC)                 // 16

// Device scratch (static; no runtime allocation)
__device__ int    g_off[NEXP + 1];
__device__ int    g_cnt[NEXP];
__device__ int    g_tile_e[NTILES];
__device__ int    g_src[MAXROWS];
__device__ int    g_pos[NK];
__device__ __half g_xp[(size_t)MAXROWS * DM];
__device__ __half g_h [(size_t)MAXROWS * DH];
__device__ float  g_op[(size_t)MAXROWS * DM];
__device__ __half g_w1h[WELEMS];
__device__ __half g_w2h[WELEMS];
__device__ __half g_w3h[WELEMS];

// ---------------------------------------------------------------------------
__device__ __forceinline__ uint32_t smem_u32(const void* p) {
    uint32_t a;
    asm("{ .reg .u64 t; cvta.to.shared.u64 t, %1; cvt.u32.u64 %0, t; }" : "=r"(a) : "l"(p));
    return a;
}
#define CP_ASYNC16(dst, src) \
    asm volatile("cp.async.cg.shared.global [%0], [%1], 16;" :: "r"(dst), "l"(src))
#define CP_COMMIT()   asm volatile("cp.async.commit_group;" ::: "memory")
#define CP_WAIT1()    asm volatile("cp.async.wait_group 1;" ::: "memory")
#define CP_WAIT0()    asm volatile("cp.async.wait_group 0;" ::: "memory")

#define LDSM4(r0, r1, r2, r3, addr)                                              \
    asm volatile("ldmatrix.sync.aligned.m8n8.x4.shared.b16 {%0,%1,%2,%3}, [%4];" \
        : "=r"(r0), "=r"(r1), "=r"(r2), "=r"(r3) : "r"(addr))
#define LDSM4T(r0, r1, r2, r3, addr)                                             \
    asm volatile("ldmatrix.sync.aligned.m8n8.x4.trans.shared.b16 {%0,%1,%2,%3}, [%4];" \
        : "=r"(r0), "=r"(r1), "=r"(r2), "=r"(r3) : "r"(addr))

#define MMA_F16(d, a, b0_, b1_)                                                  \
    asm volatile("mma.sync.aligned.m16n8k16.row.col.f32.f16.f16.f32 "            \
        "{%0,%1,%2,%3},{%4,%5,%6,%7},{%8,%9},{%0,%1,%2,%3};"                     \
        : "+f"((d)[0]), "+f"((d)[1]), "+f"((d)[2]), "+f"((d)[3])                 \
        : "r"((a)[0]), "r"((a)[1]), "r"((a)[2]), "r"((a)[3]),                    \
          "r"(b0_), "r"(b1_))

// ---------------------------------------------------------------------------
__global__ void k_setup(const int* __restrict__ bspe) {
    if (threadIdx.x == 0 && blockIdx.x == 0) {
        int off = 0;
        for (int e = 0; e < NEXP; e++) {
            g_off[e] = off;
            g_cnt[e] = 0;
            int ntile = (bspe[e] + RTILE - 1) >> 7;
            int t0 = off >> 7;
            for (int j = 0; j < ntile; j++) g_tile_e[t0 + j] = e;
            off += ntile * RTILE;
        }
        g_off[NEXP] = off;
        for (int t = off >> 7; t < NTILES; t++) g_tile_e[t] = -1;
    }
}

__global__ void k_scatter(const int* __restrict__ idx) {
    int i = blockIdx.x * blockDim.x + threadIdx.x;
    if (i < NK) {
        int e   = idx[i];
        int p   = atomicAdd(&g_cnt[e], 1);
        int pos = g_off[e] + p;
        g_pos[i]   = pos;
        g_src[pos] = i;
    }
}

// Gather x -> g_xp (fp16). One block per permuted row.
__global__ void k_gather(const float* __restrict__ x, const int* __restrict__ bspe) {
    int r = blockIdx.x;
    int e = g_tile_e[r >> 7];
    bool valid = (e >= 0) && ((r - g_off[e]) < bspe[e]);
    __half2* dst = reinterpret_cast<__half2*>(g_xp + (size_t)r * DM) + threadIdx.x * 2;
    if (valid) {
        int tok = g_src[r] / TOPK;
        float4 v = reinterpret_cast<const float4*>(x + (size_t)tok * DM)[threadIdx.x];
        dst[0] = __floats2half2_rn(v.x, v.y);
        dst[1] = __floats2half2_rn(v.z, v.w);
    } else {
        dst[0] = __floats2half2_rn(0.f, 0.f);
        dst[1] = __floats2half2_rn(0.f, 0.f);
    }
}

// Weights fp32 -> fp16 (RNE). cvtw13: grid (WELEMS/4/256, 2) for w1,w3.
__global__ void k_cvtw13(const float* __restrict__ w1, const float* __restrict__ w3) {
    size_t i = (size_t)blockIdx.x * blockDim.x + threadIdx.x;
    const float4* src = (blockIdx.y == 0) ? (const float4*)w1 : (const float4*)w3;
    __half2* dst      = (blockIdx.y == 0) ? (__half2*)g_w1h   : (__half2*)g_w3h;
    float4 v = src[i];
    dst[2 * i]     = __floats2half2_rn(v.x, v.y);
    dst[2 * i + 1] = __floats2half2_rn(v.z, v.w);
}
__global__ void k_cvtw2(const float* __restrict__ w2) {
    size_t i = (size_t)blockIdx.x * blockDim.x + threadIdx.x;
    float4 v = ((const float4*)w2)[i];
    __half2* dst = (__half2*)g_w2h;
    dst[2 * i]     = __floats2half2_rn(v.x, v.y);
    dst[2 * i + 1] = __floats2half2_rn(v.z, v.w);
}

// ---------------------------------------------------------------------------
// GEMM1: h = silu(x @ w1) * (x @ w3).  512 thr, block 128M x 128N(x2), KC=64.
// smem/buf: A 128x72h (18432B) | B1 64x136h (17408B) | B3 (17408B) = 53248B, 3 bufs.
// ---------------------------------------------------------------------------
#define G1_BUFB 53248
#define G1_DYN  (3 * G1_BUFB)      // 159744
#define G2_BUFB 52224
#define G2_DYN  (3 * G2_BUFB)      // 156672

__global__ __launch_bounds__(512, 1)
void k_gemm1() {
    extern __shared__ __align__(16) unsigned char dsm[];
    int e = g_tile_e[blockIdx.y];
    if (e < 0) return;
    const __half* W1 = g_w1h + (size_t)e * DM * DH;
    const __half* W3 = g_w3h + (size_t)e * DM * DH;
    int row0 = blockIdx.y * 128;
    int col0 = blockIdx.x * 128;

    int tid  = threadIdx.x;
    int lane = tid & 31;
    int wid  = tid >> 5;          // 0..15
    int wy   = wid >> 2;          // 0..3 -> m0 = wy*32
    int wx   = wid & 3;           // 0..3 -> n0 = wx*32

    uint32_t sbase = smem_u32(dsm);

    auto load_chunk = [&](int c, int b) {
        int k0 = c * KC;
        uint32_t bb = sbase + (uint32_t)b * G1_BUFB;
        #pragma unroll
        for (int i = 0; i < 2; i++) {               // A: 128 rows x 8 segs = 1024 ops
            int idx = tid + i * 512;
            int r = idx >> 3, s = idx & 7;
            CP_ASYNC16(bb + (uint32_t)(r * 144 + s * 16),
                       g_xp + (size_t)(row0 + r) * DM + k0 + s * 8);
        }
        #pragma unroll
        for (int i = 0; i < 4; i++) {               // B1|B3: 2 x 64 rows x 16 segs = 2048 ops
            int idx = tid + i * 512;
            int m = idx >> 10;
            int j = idx & 1023;
            int k = j >> 4, s = j & 15;
            const __half* src = (m ? W3 : W1) + (size_t)(k0 + k) * DH + col0 + s * 8;
            CP_ASYNC16(bb + 18432u + (uint32_t)m * 17408u + (uint32_t)(k * 272 + s * 16), src);
        }
        CP_COMMIT();
    };

    float acc1[2][4][4] = {};
    float acc3[2][4][4] = {};

    uint32_t aoff = (uint32_t)(((lane & 15) + wy * 32) * 144 + (lane >> 4) * 16);
    uint32_t boff = 18432u + (uint32_t)((lane & 15) * 272 + ((lane >> 4) * 8 + wx * 32) * 2);

    load_chunk(0, 0);
    load_chunk(1, 1);

    for (int c = 0; c < NCHUNK; c++) {
        if (c < NCHUNK - 1) CP_WAIT1(); else CP_WAIT0();
        __syncthreads();
        if (c + 2 < NCHUNK) load_chunk(c + 2, (c + 2) % 3);

        uint32_t bb = sbase + (uint32_t)(c % 3) * G1_BUFB;
        #pragma unroll
        for (int ks = 0; ks < 4; ks++) {
            uint32_t af[2][4];
            LDSM4(af[0][0], af[0][1], af[0][2], af[0][3], bb + aoff + ks * 32);
            LDSM4(af[1][0], af[1][1], af[1][2], af[1][3], bb + aoff + 2304 + ks * 32);
            uint32_t b1f[8], b3f[8];
            LDSM4T(b1f[0], b1f[1], b1f[2], b1f[3], bb + boff + ks * 4352);
            LDSM4T(b1f[4], b1f[5], b1f[6], b1f[7], bb + boff + ks * 4352 + 32);
            LDSM4T(b3f[0], b3f[1], b3f[2], b3f[3], bb + boff + 17408 + ks * 4352);
            LDSM4T(b3f[4], b3f[5], b3f[6], b3f[7], bb + boff + 17408 + ks * 4352 + 32);
            #pragma unroll
            for (int mt = 0; mt < 2; mt++)
                #pragma unroll
                for (int nt = 0; nt < 4; nt++) {
                    MMA_F16(acc1[mt][nt], af[mt], b1f[2 * nt], b1f[2 * nt + 1]);
                    MMA_F16(acc3[mt][nt], af[mt], b3f[2 * nt], b3f[2 * nt + 1]);
                }
        }
    }

    // Epilogue: SwiGLU -> half2 -> g_h
    int rbase = row0 + wy * 32 + (lane >> 2);
    int cbase = col0 + wx * 32 + 2 * (lane & 3);
    #pragma unroll
    for (int mt = 0; mt < 2; mt++)
        #pragma unroll
        for (int nt = 0; nt < 4; nt++) {
            int col = cbase + nt * 8;
            #pragma unroll
            for (int h = 0; h < 2; h++) {
                int r = rbase + mt * 16 + h * 8;
                float a0 = acc1[mt][nt][2 * h], a1 = acc1[mt][nt][2 * h + 1];
                float s0 = a0 / (1.f + __expf(-a0));
                float s1 = a1 / (1.f + __expf(-a1));
                *reinterpret_cast<__half2*>(g_h + (size_t)r * DH + col) =
                    __floats2half2_rn(s0 * acc3[mt][nt][2 * h], s1 * acc3[mt][nt][2 * h + 1]);
            }
        }
}

// ---------------------------------------------------------------------------
// GEMM2: out_perm = h @ w2.  512 thr, block 128M x 256N, KC=64.
// smem/buf: A 128x72h (18432B) | B 64x264h (33792B) = 52224B, 3 bufs.
// ---------------------------------------------------------------------------
__global__ __launch_bounds__(512, 1)
void k_gemm2() {
    extern __shared__ __align__(16) unsigned char dsm[];
    int e = g_tile_e[blockIdx.y];
    if (e < 0) return;
    const __half* W2 = g_w2h + (size_t)e * DH * DM;
    int row0 = blockIdx.y * 128;
    int col0 = blockIdx.x * 256;

    int tid  = threadIdx.x;
    int lane = tid & 31;
    int wid  = tid >> 5;
    int wy   = wid >> 2;          // m0 = wy*32
    int wx   = wid & 3;           // n0 = wx*64

    uint32_t sbase = smem_u32(dsm);

    auto load_chunk = [&](int c, int b) {
        int k0 = c * KC;
        uint32_t bb = sbase + (uint32_t)b * G2_BUFB;
        #pragma unroll
        for (int i = 0; i < 2; i++) {               // A
            int idx = tid + i * 512;
            int r = idx >> 3, s = idx & 7;
            CP_ASYNC16(bb + (uint32_t)(r * 144 + s * 16),
                       g_h + (size_t)(row0 + r) * DH + k0 + s * 8);
        }
        #pragma unroll
        for (int i = 0; i < 4; i++) {               // B: 64 rows x 32 segs = 2048 ops
            int idx = tid + i * 512;
            int k = idx >> 5, s = idx & 31;
            CP_ASYNC16(bb + 18432u + (uint32_t)(k * 528 + s * 16),
                       W2 + (size_t)(k0 + k) * DM + col0 + s * 8);
        }
        CP_COMMIT();
    };

    float acc[2][8][4] = {};

    uint32_t aoff = (uint32_t)(((lane & 15) + wy * 32) * 144 + (lane >> 4) * 16);
    uint32_t boff = 18432u + (uint32_t)((lane & 15) * 528 + ((lane >> 4) * 8 + wx * 64) * 2);

    load_chunk(0, 0);
    load_chunk(1, 1);

    for (int c = 0; c < NCHUNK; c++) {
        if (c < NCHUNK - 1) CP_WAIT1(); else CP_WAIT0();
        __syncthreads();
        if (c + 2 < NCHUNK) load_chunk(c + 2, (c + 2) % 3);

        uint32_t bb = sbase + (uint32_t)(c % 3) * G2_BUFB;
        #pragma unroll
        for (int ks = 0; ks < 4; ks++) {
            uint32_t af[2][4];
            LDSM4(af[0][0], af[0][1], af[0][2], af[0][3], bb + aoff + ks * 32);
            LDSM4(af[1][0], af[1][1], af[1][2], af[1][3], bb + aoff + 2304 + ks * 32);
            uint32_t bf[16];                         // 8 n-tiles x 2 regs
            #pragma unroll
            for (int q = 0; q < 4; q++)
                LDSM4T(bf[4 * q], bf[4 * q + 1], bf[4 * q + 2], bf[4 * q + 3],
                       bb + boff + ks * 8448 + q * 32);
            #pragma unroll
            for (int mt = 0; mt < 2; mt++)
                #pragma unroll
                for (int nt = 0; nt < 8; nt++)
                    MMA_F16(acc[mt][nt], af[mt], bf[2 * nt], bf[2 * nt + 1]);
        }
    }

    int rbase = row0 + wy * 32 + (lane >> 2);
    int cbase = col0 + wx * 64 + 2 * (lane & 3);
    #pragma unroll
    for (int mt = 0; mt < 2; mt++)
        #pragma unroll
        for (int nt = 0; nt < 8; nt++) {
            int col = cbase + nt * 8;
            #pragma unroll
            for (int h = 0; h < 2; h++) {
                int r = rbase + mt * 16 + h * 8;
                float2 o;
                o.x = acc[mt][nt][2 * h];
                o.y = acc[mt][nt][2 * h + 1];
                *reinterpret_cast<float2*>(g_op + (size_t)r * DM + col) = o;
            }
        }
}

// ---------------------------------------------------------------------------
__global__ void k_combine(const float* __restrict__ ew, float* __restrict__ out) {
    int n = blockIdx.x;
    int c = threadIdx.x;
    float wa = ew[n * TOPK + 0];
    float wb = ew[n * TOPK + 1];
    int pa = g_pos[n * TOPK + 0];
    int pb = g_pos[n * TOPK + 1];
    float4 a = reinterpret_cast<const float4*>(g_op + (size_t)pa * DM)[c];
    float4 b = reinterpret_cast<const float4*>(g_op + (size_t)pb * DM)[c];
    float4 o;
    o.x = wa * a.x + wb * b.x;
    o.y = wa * a.y + wb * b.y;
    o.z = wa * a.z + wb * b.z;
    o.w = wa * a.w + wb * b.w;
    reinterpret_cast<float4*>(out + (size_t)n * DM)[c] = o;
}

// ---------------------------------------------------------------------------
extern "C" void kernel_launch(void* const* d_in, const int* in_sizes, int n_in,
                              void* d_out, int out_size) {
    const float* x    = (const float*)d_in[0];
    const float* ew   = (const float*)d_in[1];
    const int*   idx  = (const int*)  d_in[2];
    const int*   bspe = (const int*)  d_in[3];
    const float* w1   = (const float*)d_in[4];
    const float* w2   = (const float*)d_in[5];
    const float* w3   = (const float*)d_in[6];
    float* out = (float*)d_out;

    static cudaStream_t s2 = nullptr;
    static cudaEvent_t evStart = nullptr, ev13 = nullptr, ev2 = nullptr;
    if (!s2) {
        cudaStreamCreateWithFlags(&s2, cudaStreamNonBlocking);
        cudaEventCreateWithFlags(&evStart, cudaEventDisableTiming);
        cudaEventCreateWithFlags(&ev13, cudaEventDisableTiming);
        cudaEventCreateWithFlags(&ev2, cudaEventDisableTiming);
        cudaFuncSetAttribute(k_gemm1, cudaFuncAttributeMaxDynamicSharedMemorySize, G1_DYN);
        cudaFuncSetAttribute(k_gemm2, cudaFuncAttributeMaxDynamicSharedMemorySize, G2_DYN);
    }

    // Fork: weight conversion on s2, permute pipeline on main stream.
    cudaEventRecord(evStart, 0);
    cudaStreamWaitEvent(s2, evStart, 0);
    k_cvtw13<<<dim3(WELEMS / 4 / 256, 2), 256, 0, s2>>>(w1, w3);
    cudaEventRecord(ev13, s2);
    k_cvtw2<<<WELEMS / 4 / 256, 256, 0, s2>>>(w2);
    cudaEventRecord(ev2, s2);

    k_setup<<<1, 32>>>(bspe);
    k_scatter<<<NK / 256, 256>>>(idx);
    k_gather<<<MAXROWS, 256>>>(x, bspe);

    cudaStreamWaitEvent(0, ev13, 0);
    k_gemm1<<<dim3(DH / 128, NTILES), 512, G1_DYN>>>();
    cudaStreamWaitEvent(0, ev2, 0);
    k_gemm2<<<dim3(DM / 256, NTILES), 512, G2_DYN>>>();

    k_combine<<<N_TOK, 256>>>(ew, out);
}

// round 9
// speedup vs baseline: 1.0480x; 1.0480x over previous
#include <cuda_runtime.h>
#include <cuda_fp16.h>
#include <cstdint>
#include <math.h>

// ---------------------------------------------------------------------------
// Dropless MoE: N=4096, K=2, E=8, D=H=1024, fp32 in/out.
// GEMMs via mma.sync.m16n8k16 fp16 (fp32 accum), 256-thread CTAs (2/SM),
// round-6 tile shapes + 3-stage cp.async ring, single barrier per chunk.
// Weight conversion overlapped on a forked stream.
// ---------------------------------------------------------------------------

#define N_TOK   4096
#define TOPK    2
#define NEXP    8
#define DM      1024
#define DH      1024
#define NK      (N_TOK * TOPK)            // 8192
#define RTILE   128
#define MAXROWS (NK + NEXP * RTILE)       // 9216
#define NTILES  (MAXROWS / RTILE)         // 72
#define WELEMS  (NEXP * DM * DH)          // 8388608
#define KC      64                        // K-chunk (4 x k16 MMA steps)
#define NCHUNK  (DM / KC)                 // 16

// Device scratch (static; no runtime allocation)
__device__ int    g_off[NEXP + 1];
__device__ int    g_cnt[NEXP];
__device__ int    g_tile_e[NTILES];
__device__ int    g_src[MAXROWS];
__device__ int    g_pos[NK];
__device__ __half g_xp[(size_t)MAXROWS * DM];
__device__ __half g_h [(size_t)MAXROWS * DH];
__device__ float  g_op[(size_t)MAXROWS * DM];
__device__ __half g_w1h[WELEMS];
__device__ __half g_w2h[WELEMS];
__device__ __half g_w3h[WELEMS];

// ---------------------------------------------------------------------------
__device__ __forceinline__ uint32_t smem_u32(const void* p) {
    uint32_t a;
    asm("{ .reg .u64 t; cvta.to.shared.u64 t, %1; cvt.u32.u64 %0, t; }" : "=r"(a) : "l"(p));
    return a;
}
#define CP_ASYNC16(dst, src) \
    asm volatile("cp.async.cg.shared.global [%0], [%1], 16;" :: "r"(dst), "l"(src))
#define CP_COMMIT()   asm volatile("cp.async.commit_group;" ::: "memory")
#define CP_WAIT1()    asm volatile("cp.async.wait_group 1;" ::: "memory")
#define CP_WAIT0()    asm volatile("cp.async.wait_group 0;" ::: "memory")

#define LDSM4(r0, r1, r2, r3, addr)                                              \
    asm volatile("ldmatrix.sync.aligned.m8n8.x4.shared.b16 {%0,%1,%2,%3}, [%4];" \
        : "=r"(r0), "=r"(r1), "=r"(r2), "=r"(r3) : "r"(addr))
#define LDSM4T(r0, r1, r2, r3, addr)                                             \
    asm volatile("ldmatrix.sync.aligned.m8n8.x4.trans.shared.b16 {%0,%1,%2,%3}, [%4];" \
        : "=r"(r0), "=r"(r1), "=r"(r2), "=r"(r3) : "r"(addr))

#define MMA_F16(d, a, b0_, b1_)                                                  \
    asm volatile("mma.sync.aligned.m16n8k16.row.col.f32.f16.f16.f32 "            \
        "{%0,%1,%2,%3},{%4,%5,%6,%7},{%8,%9},{%0,%1,%2,%3};"                     \
        : "+f"((d)[0]), "+f"((d)[1]), "+f"((d)[2]), "+f"((d)[3])                 \
        : "r"((a)[0]), "r"((a)[1]), "r"((a)[2]), "r"((a)[3]),                    \
          "r"(b0_), "r"(b1_))

// ---------------------------------------------------------------------------
__global__ void k_setup(const int* __restrict__ bspe) {
    if (threadIdx.x == 0 && blockIdx.x == 0) {
        int off = 0;
        for (int e = 0; e < NEXP; e++) {
            g_off[e] = off;
            g_cnt[e] = 0;
            int ntile = (bspe[e] + RTILE - 1) >> 7;
            int t0 = off >> 7;
            for (int j = 0; j < ntile; j++) g_tile_e[t0 + j] = e;
            off += ntile * RTILE;
        }
        g_off[NEXP] = off;
        for (int t = off >> 7; t < NTILES; t++) g_tile_e[t] = -1;
    }
}

__global__ void k_scatter(const int* __restrict__ idx) {
    int i = blockIdx.x * blockDim.x + threadIdx.x;
    if (i < NK) {
        int e   = idx[i];
        int p   = atomicAdd(&g_cnt[e], 1);
        int pos = g_off[e] + p;
        g_pos[i]   = pos;
        g_src[pos] = i;
    }
}

// Gather x -> g_xp (fp16). One block per permuted row.
__global__ void k_gather(const float* __restrict__ x, const int* __restrict__ bspe) {
    int r = blockIdx.x;
    int e = g_tile_e[r >> 7];
    bool valid = (e >= 0) && ((r - g_off[e]) < bspe[e]);
    __half2* dst = reinterpret_cast<__half2*>(g_xp + (size_t)r * DM) + threadIdx.x * 2;
    if (valid) {
        int tok = g_src[r] / TOPK;
        float4 v = reinterpret_cast<const float4*>(x + (size_t)tok * DM)[threadIdx.x];
        dst[0] = __floats2half2_rn(v.x, v.y);
        dst[1] = __floats2half2_rn(v.z, v.w);
    } else {
        dst[0] = __floats2half2_rn(0.f, 0.f);
        dst[1] = __floats2half2_rn(0.f, 0.f);
    }
}

// Weights fp32 -> fp16 (RNE).
__global__ void k_cvtw13(const float* __restrict__ w1, const float* __restrict__ w3) {
    size_t i = (size_t)blockIdx.x * blockDim.x + threadIdx.x;
    const float4* src = (blockIdx.y == 0) ? (const float4*)w1 : (const float4*)w3;
    __half2* dst      = (blockIdx.y == 0) ? (__half2*)g_w1h   : (__half2*)g_w3h;
    float4 v = src[i];
    dst[2 * i]     = __floats2half2_rn(v.x, v.y);
    dst[2 * i + 1] = __floats2half2_rn(v.z, v.w);
}
__global__ void k_cvtw2(const float* __restrict__ w2) {
    size_t i = (size_t)blockIdx.x * blockDim.x + threadIdx.x;
    float4 v = ((const float4*)w2)[i];
    __half2* dst = (__half2*)g_w2h;
    dst[2 * i]     = __floats2half2_rn(v.x, v.y);
    dst[2 * i + 1] = __floats2half2_rn(v.z, v.w);
}

// ---------------------------------------------------------------------------
// GEMM1: h = silu(x @ w1) * (x @ w3).  Block 128M x 64N(x2), KC=64, 256 thr.
// smem/buf: A 128x72h (18432B) | B1 64x72h (9216B) | B3 (9216B) = 36864B, 3 bufs.
// ---------------------------------------------------------------------------
#define G1_BUFB 36864
#define G1_DYN  (3 * G1_BUFB)      // 110592
#define G2_BUFB 35840
#define G2_DYN  (3 * G2_BUFB)      // 107520

__global__ __launch_bounds__(256, 2)
void k_gemm1() {
    extern __shared__ __align__(16) unsigned char dsm[];
    int e = g_tile_e[blockIdx.y];
    if (e < 0) return;
    const __half* W1 = g_w1h + (size_t)e * DM * DH;
    const __half* W3 = g_w3h + (size_t)e * DM * DH;
    int row0 = blockIdx.y * 128;
    int col0 = blockIdx.x * 64;

    int tid  = threadIdx.x;
    int lane = tid & 31;
    int wid  = tid >> 5;
    int wy   = wid >> 1;          // m0 = wy*32
    int wx   = wid & 1;           // n0 = wx*32

    uint32_t sbase = smem_u32(dsm);

    auto load_chunk = [&](int c, int b) {
        int k0 = c * KC;
        uint32_t bb = sbase + (uint32_t)b * G1_BUFB;
        #pragma unroll
        for (int i = 0; i < 4; i++) {               // A: 128 rows x 8 segs
            int idx = tid + i * 256;
            int r = idx >> 3, s = idx & 7;
            CP_ASYNC16(bb + (uint32_t)(r * 144 + s * 16),
                       g_xp + (size_t)(row0 + r) * DM + k0 + s * 8);
        }
        #pragma unroll
        for (int i = 0; i < 4; i++) {               // B1 then B3: 64 rows x 8 segs each
            int idx = tid + i * 256;
            int m = idx >> 9;
            int j = idx & 511;
            int k = j >> 3, s = j & 7;
            const __half* src = (m ? W3 : W1) + (size_t)(k0 + k) * DH + col0 + s * 8;
            CP_ASYNC16(bb + 18432u + (uint32_t)m * 9216u + (uint32_t)(k * 144 + s * 16), src);
        }
        CP_COMMIT();
    };

    float acc1[2][4][4] = {};
    float acc3[2][4][4] = {};

    uint32_t aoff = (uint32_t)(((lane & 15) + wy * 32) * 144 + (lane >> 4) * 16);
    uint32_t boff = 18432u + (uint32_t)((lane & 15) * 144 + ((lane >> 4) * 8 + wx * 32) * 2);

    load_chunk(0, 0);
    load_chunk(1, 1);

    for (int c = 0; c < NCHUNK; c++) {
        if (c < NCHUNK - 1) CP_WAIT1(); else CP_WAIT0();
        __syncthreads();
        if (c + 2 < NCHUNK) load_chunk(c + 2, (c + 2) % 3);

        uint32_t bb = sbase + (uint32_t)(c % 3) * G1_BUFB;
        #pragma unroll
        for (int ks = 0; ks < 4; ks++) {
            uint32_t af[2][4];
            LDSM4(af[0][0], af[0][1], af[0][2], af[0][3], bb + aoff + ks * 32);
            LDSM4(af[1][0], af[1][1], af[1][2], af[1][3], bb + aoff + 2304 + ks * 32);
            uint32_t b1f[8], b3f[8];
            LDSM4T(b1f[0], b1f[1], b1f[2], b1f[3], bb + boff + ks * 2304);
            LDSM4T(b1f[4], b1f[5], b1f[6], b1f[7], bb + boff + ks * 2304 + 32);
            LDSM4T(b3f[0], b3f[1], b3f[2], b3f[3], bb + boff + 9216 + ks * 2304);
            LDSM4T(b3f[4], b3f[5], b3f[6], b3f[7], bb + boff + 9216 + ks * 2304 + 32);
            #pragma unroll
            for (int mt = 0; mt < 2; mt++)
                #pragma unroll
                for (int nt = 0; nt < 4; nt++) {
                    MMA_F16(acc1[mt][nt], af[mt], b1f[2 * nt], b1f[2 * nt + 1]);
                    MMA_F16(acc3[mt][nt], af[mt], b3f[2 * nt], b3f[2 * nt + 1]);
                }
        }
    }

    // Epilogue: SwiGLU -> half2 -> g_h
    int rbase = row0 + wy * 32 + (lane >> 2);
    int cbase = col0 + wx * 32 + 2 * (lane & 3);
    #pragma unroll
    for (int mt = 0; mt < 2; mt++)
        #pragma unroll
        for (int nt = 0; nt < 4; nt++) {
            int col = cbase + nt * 8;
            #pragma unroll
            for (int h = 0; h < 2; h++) {
                int r = rbase + mt * 16 + h * 8;
                float a0 = acc1[mt][nt][2 * h], a1 = acc1[mt][nt][2 * h + 1];
                float s0 = a0 / (1.f + __expf(-a0));
                float s1 = a1 / (1.f + __expf(-a1));
                *reinterpret_cast<__half2*>(g_h + (size_t)r * DH + col) =
                    __floats2half2_rn(s0 * acc3[mt][nt][2 * h], s1 * acc3[mt][nt][2 * h + 1]);
            }
        }
}

// ---------------------------------------------------------------------------
// GEMM2: out_perm = h @ w2.  Block 128M x 128N, KC=64, 256 thr.
// smem/buf: A 128x72h (18432B) | B 64x136h (17408B) = 35840B, 3 bufs.
// ---------------------------------------------------------------------------
__global__ __launch_bounds__(256, 2)
void k_gemm2() {
    extern __shared__ __align__(16) unsigned char dsm[];
    int e = g_tile_e[blockIdx.y];
    if (e < 0) return;
    const __half* W2 = g_w2h + (size_t)e * DH * DM;
    int row0 = blockIdx.y * 128;
    int col0 = blockIdx.x * 128;

    int tid  = threadIdx.x;
    int lane = tid & 31;
    int wid  = tid >> 5;
    int wy   = wid >> 1;          // m0 = wy*32
    int wx   = wid & 1;           // n0 = wx*64

    uint32_t sbase = smem_u32(dsm);

    auto load_chunk = [&](int c, int b) {
        int k0 = c * KC;
        uint32_t bb = sbase + (uint32_t)b * G2_BUFB;
        #pragma unroll
        for (int i = 0; i < 4; i++) {               // A
            int idx = tid + i * 256;
            int r = idx >> 3, s = idx & 7;
            CP_ASYNC16(bb + (uint32_t)(r * 144 + s * 16),
                       g_h + (size_t)(row0 + r) * DH + k0 + s * 8);
        }
        #pragma unroll
        for (int i = 0; i < 4; i++) {               // B: 64 rows x 16 segs
            int idx = tid + i * 256;
            int k = idx >> 4, s = idx & 15;
            CP_ASYNC16(bb + 18432u + (uint32_t)(k * 272 + s * 16),
                       W2 + (size_t)(k0 + k) * DM + col0 + s * 8);
        }
        CP_COMMIT();
    };

    float acc[2][8][4] = {};

    uint32_t aoff = (uint32_t)(((lane & 15) + wy * 32) * 144 + (lane >> 4) * 16);
    uint32_t boff = 18432u + (uint32_t)((lane & 15) * 272 + ((lane >> 4) * 8 + wx * 64) * 2);

    load_chunk(0, 0);
    load_chunk(1, 1);

    for (int c = 0; c < NCHUNK; c++) {
        if (c < NCHUNK - 1) CP_WAIT1(); else CP_WAIT0();
        __syncthreads();
        if (c + 2 < NCHUNK) load_chunk(c + 2, (c + 2) % 3);

        uint32_t bb = sbase + (uint32_t)(c % 3) * G2_BUFB;
        #pragma unroll
        for (int ks = 0; ks < 4; ks++) {
            uint32_t af[2][4];
            LDSM4(af[0][0], af[0][1], af[0][2], af[0][3], bb + aoff + ks * 32);
            LDSM4(af[1][0], af[1][1], af[1][2], af[1][3], bb + aoff + 2304 + ks * 32);
            uint32_t bf[16];                         // 8 n-tiles x 2 regs
            #pragma unroll
            for (int q = 0; q < 4; q++)
                LDSM4T(bf[4 * q], bf[4 * q + 1], bf[4 * q + 2], bf[4 * q + 3],
                       bb + boff + ks * 4352 + q * 32);
            #pragma unroll
            for (int mt = 0; mt < 2; mt++)
                #pragma unroll
                for (int nt = 0; nt < 8; nt++)
                    MMA_F16(acc[mt][nt], af[mt], bf[2 * nt], bf[2 * nt + 1]);
        }
    }

    int rbase = row0 + wy * 32 + (lane >> 2);
    int cbase = col0 + wx * 64 + 2 * (lane & 3);
    #pragma unroll
    for (int mt = 0; mt < 2; mt++)
        #pragma unroll
        for (int nt = 0; nt < 8; nt++) {
            int col = cbase + nt * 8;
            #pragma unroll
            for (int h = 0; h < 2; h++) {
                int r = rbase + mt * 16 + h * 8;
                float2 o;
                o.x = acc[mt][nt][2 * h];
                o.y = acc[mt][nt][2 * h + 1];
                *reinterpret_cast<float2*>(g_op + (size_t)r * DM + col) = o;
            }
        }
}

// ---------------------------------------------------------------------------
__global__ void k_combine(const float* __restrict__ ew, float* __restrict__ out) {
    int n = blockIdx.x;
    int c = threadIdx.x;
    float wa = ew[n * TOPK + 0];
    float wb = ew[n * TOPK + 1];
    int pa = g_pos[n * TOPK + 0];
    int pb = g_pos[n * TOPK + 1];
    float4 a = reinterpret_cast<const float4*>(g_op + (size_t)pa * DM)[c];
    float4 b = reinterpret_cast<const float4*>(g_op + (size_t)pb * DM)[c];
    float4 o;
    o.x = wa * a.x + wb * b.x;
    o.y = wa * a.y + wb * b.y;
    o.z = wa * a.z + wb * b.z;
    o.w = wa * a.w + wb * b.w;
    reinterpret_cast<float4*>(out + (size_t)n * DM)[c] = o;
}

// ---------------------------------------------------------------------------
extern "C" void kernel_launch(void* const* d_in, const int* in_sizes, int n_in,
                              void* d_out, int out_size) {
    const float* x    = (const float*)d_in[0];
    const float* ew   = (const float*)d_in[1];
    const int*   idx  = (const int*)  d_in[2];
    const int*   bspe = (const int*)  d_in[3];
    const float* w1   = (const float*)d_in[4];
    const float* w2   = (const float*)d_in[5];
    const float* w3   = (const float*)d_in[6];
    float* out = (float*)d_out;

    static cudaStream_t s2 = nullptr;
    static cudaEvent_t evStart = nullptr, ev13 = nullptr, ev2 = nullptr;
    if (!s2) {
        cudaStreamCreateWithFlags(&s2, cudaStreamNonBlocking);
        cudaEventCreateWithFlags(&evStart, cudaEventDisableTiming);
        cudaEventCreateWithFlags(&ev13, cudaEventDisableTiming);
        cudaEventCreateWithFlags(&ev2, cudaEventDisableTiming);
        cudaFuncSetAttribute(k_gemm1, cudaFuncAttributeMaxDynamicSharedMemorySize, G1_DYN);
        cudaFuncSetAttribute(k_gemm2, cudaFuncAttributeMaxDynamicSharedMemorySize, G2_DYN);
    }

    // Fork: weight conversion on s2 overlaps permute pipeline on main stream.
    cudaEventRecord(evStart, 0);
    cudaStreamWaitEvent(s2, evStart, 0);
    k_cvtw13<<<dim3(WELEMS / 4 / 256, 2), 256, 0, s2>>>(w1, w3);
    cudaEventRecord(ev13, s2);
    k_cvtw2<<<WELEMS / 4 / 256, 256, 0, s2>>>(w2);
    cudaEventRecord(ev2, s2);

    k_setup<<<1, 32>>>(bspe);
    k_scatter<<<NK / 256, 256>>>(idx);
    k_gather<<<MAXROWS, 256>>>(x, bspe);

    cudaStreamWaitEvent(0, ev13, 0);
    k_gemm1<<<dim3(DH / 64, NTILES), 256, G1_DYN>>>();
    cudaStreamWaitEvent(0, ev2, 0);
    k_gemm2<<<dim3(DM / 128, NTILES), 256, G2_DYN>>>();

    k_combine<<<N_TOK, 256>>>(ew, out);
}

// round 14
// speedup vs baseline: 1.0598x; 1.0113x over previous
#include <cuda_runtime.h>
#include <cuda_fp16.h>
#include <cstdint>
#include <math.h>

// ---------------------------------------------------------------------------
// Dropless MoE: N=4096, K=2, E=8, D=H=1024, fp32 in/out.
// GEMMs fused into ONE persistent work-stealing kernel (2 CTAs/SM):
//   tiles 0..1151    : gemm1 (x@w1, x@w3, SwiGLU) -> g_h   (16 x-tiles/row)
//   tiles 1152..1727 : gemm2 (h@w2) -> g_op, gated on g_done1[y]==16
// mma.sync.m16n8k16 fp16 (fp32 accum), 3-stage cp.async ring.
// Weight conversion overlapped on a forked stream.
// ---------------------------------------------------------------------------

#define N_TOK   4096
#define TOPK    2
#define NEXP    8
#define DM      1024
#define DH      1024
#define NK      (N_TOK * TOPK)            // 8192
#define RTILE   128
#define MAXROWS (NK + NEXP * RTILE)       // 9216
#define NTILES  (MAXROWS / RTILE)         // 72
#define WELEMS  (NEXP * DM * DH)          // 8388608
#define KC      64
#define NCHUNK  (DM / KC)                 // 16
#define T1      (NTILES * 16)             // 1152 gemm1 tiles (64-wide N)
#define T2      (NTILES * 8)              // 576 gemm2 tiles (128-wide N)
#define PERSIST 296                       // 2 CTAs x 148 SMs

// Device scratch (static; no runtime allocation)
__device__ int    g_off[NEXP + 1];
__device__ int    g_cnt[NEXP];
__device__ int    g_tile_e[NTILES];
__device__ int    g_src[MAXROWS];
__device__ int    g_pos[NK];
__device__ int    g_tilectr;
__device__ int    g_done1[NTILES];
__device__ __half g_xp[(size_t)MAXROWS * DM];
__device__ __half g_h [(size_t)MAXROWS * DH];
__device__ float  g_op[(size_t)MAXROWS * DM];
__device__ __half g_w1h[WELEMS];
__device__ __half g_w2h[WELEMS];
__device__ __half g_w3h[WELEMS];

// ---------------------------------------------------------------------------
__device__ __forceinline__ uint32_t smem_u32(const void* p) {
    uint32_t a;
    asm("{ .reg .u64 t; cvta.to.shared.u64 t, %1; cvt.u32.u64 %0, t; }" : "=r"(a) : "l"(p));
    return a;
}
#define CP_ASYNC16(dst, src) \
    asm volatile("cp.async.cg.shared.global [%0], [%1], 16;" :: "r"(dst), "l"(src))
#define CP_COMMIT()   asm volatile("cp.async.commit_group;" ::: "memory")
#define CP_WAIT1()    asm volatile("cp.async.wait_group 1;" ::: "memory")
#define CP_WAIT0()    asm volatile("cp.async.wait_group 0;" ::: "memory")

#define LDSM4(r0, r1, r2, r3, addr)                                              \
    asm volatile("ldmatrix.sync.aligned.m8n8.x4.shared.b16 {%0,%1,%2,%3}, [%4];" \
        : "=r"(r0), "=r"(r1), "=r"(r2), "=r"(r3) : "r"(addr))
#define LDSM4T(r0, r1, r2, r3, addr)                                             \
    asm volatile("ldmatrix.sync.aligned.m8n8.x4.trans.shared.b16 {%0,%1,%2,%3}, [%4];" \
        : "=r"(r0), "=r"(r1), "=r"(r2), "=r"(r3) : "r"(addr))

#define MMA_F16(d, a, b0_, b1_)                                                  \
    asm volatile("mma.sync.aligned.m16n8k16.row.col.f32.f16.f16.f32 "            \
        "{%0,%1,%2,%3},{%4,%5,%6,%7},{%8,%9},{%0,%1,%2,%3};"                     \
        : "+f"((d)[0]), "+f"((d)[1]), "+f"((d)[2]), "+f"((d)[3])                 \
        : "r"((a)[0]), "r"((a)[1]), "r"((a)[2]), "r"((a)[3]),                    \
          "r"(b0_), "r"(b1_))

// ---------------------------------------------------------------------------
__global__ void k_setup(const int* __restrict__ bspe) {
    if (threadIdx.x == 0 && blockIdx.x == 0) {
        int off = 0;
        for (int e = 0; e < NEXP; e++) {
            g_off[e] = off;
            g_cnt[e] = 0;
            int ntile = (bspe[e] + RTILE - 1) >> 7;
            int t0 = off >> 7;
            for (int j = 0; j < ntile; j++) g_tile_e[t0 + j] = e;
            off += ntile * RTILE;
        }
        g_off[NEXP] = off;
        for (int t = off >> 7; t < NTILES; t++) g_tile_e[t] = -1;
        g_tilectr = 0;
        for (int t = 0; t < NTILES; t++) g_done1[t] = 0;
    }
}

__global__ void k_scatter(const int* __restrict__ idx) {
    int i = blockIdx.x * blockDim.x + threadIdx.x;
    if (i < NK) {
        int e   = idx[i];
        int p   = atomicAdd(&g_cnt[e], 1);
        int pos = g_off[e] + p;
        g_pos[i]   = pos;
        g_src[pos] = i;
    }
}

// Gather x -> g_xp (fp16). One block per permuted row.
__global__ void k_gather(const float* __restrict__ x, const int* __restrict__ bspe) {
    int r = blockIdx.x;
    int e = g_tile_e[r >> 7];
    bool valid = (e >= 0) && ((r - g_off[e]) < bspe[e]);
    __half2* dst = reinterpret_cast<__half2*>(g_xp + (size_t)r * DM) + threadIdx.x * 2;
    if (valid) {
        int tok = g_src[r] / TOPK;
        float4 v = reinterpret_cast<const float4*>(x + (size_t)tok * DM)[threadIdx.x];
        dst[0] = __floats2half2_rn(v.x, v.y);
        dst[1] = __floats2half2_rn(v.z, v.w);
    } else {
        dst[0] = __floats2half2_rn(0.f, 0.f);
        dst[1] = __floats2half2_rn(0.f, 0.f);
    }
}

// Weights fp32 -> fp16 (RNE).
__global__ void k_cvtw13(const float* __restrict__ w1, const float* __restrict__ w3) {
    size_t i = (size_t)blockIdx.x * blockDim.x + threadIdx.x;
    const float4* src = (blockIdx.y == 0) ? (const float4*)w1 : (const float4*)w3;
    __half2* dst      = (blockIdx.y == 0) ? (__half2*)g_w1h   : (__half2*)g_w3h;
    float4 v = src[i];
    dst[2 * i]     = __floats2half2_rn(v.x, v.y);
    dst[2 * i + 1] = __floats2half2_rn(v.z, v.w);
}
__global__ void k_cvtw2(const float* __restrict__ w2) {
    size_t i = (size_t)blockIdx.x * blockDim.x + threadIdx.x;
    float4 v = ((const float4*)w2)[i];
    __half2* dst = (__half2*)g_w2h;
    dst[2 * i]     = __floats2half2_rn(v.x, v.y);
    dst[2 * i + 1] = __floats2half2_rn(v.z, v.w);
}

// ---------------------------------------------------------------------------
// Tile bodies.
// gemm1 smem/buf: A 128x72h (18432B) | B1 64x72h (9216B) | B3 (9216B) = 36864B
// gemm2 smem/buf: A 128x72h (18432B) | B 64x136h (17408B)            = 35840B
// ---------------------------------------------------------------------------
#define G1_BUFB 36864
#define G2_BUFB 35840
#define P_DYN   (3 * G1_BUFB)      // 110592 (3-stage ring, max of both)

__device__ __forceinline__ void gemm1_tile(unsigned char* dsm, int y, int x,
                                           int tid, int lane, int wy, int wx) {
    int e = g_tile_e[y];
    if (e >= 0) {
        const __half* W1 = g_w1h + (size_t)e * DM * DH;
        const __half* W3 = g_w3h + (size_t)e * DM * DH;
        int row0 = y * 128;
        int col0 = x * 64;
        uint32_t sbase = smem_u32(dsm);

        auto load_chunk = [&](int c, int b) {
            int k0 = c * KC;
            uint32_t bb = sbase + (uint32_t)b * G1_BUFB;
            #pragma unroll
            for (int i = 0; i < 4; i++) {               // A: 128 rows x 8 segs
                int idx = tid + i * 256;
                int r = idx >> 3, s = idx & 7;
                CP_ASYNC16(bb + (uint32_t)(r * 144 + s * 16),
                           g_xp + (size_t)(row0 + r) * DM + k0 + s * 8);
            }
            #pragma unroll
            for (int i = 0; i < 4; i++) {               // B1|B3: 64 rows x 8 segs each
                int idx = tid + i * 256;
                int m = idx >> 9;
                int j = idx & 511;
                int k = j >> 3, s = j & 7;
                const __half* src = (m ? W3 : W1) + (size_t)(k0 + k) * DH + col0 + s * 8;
                CP_ASYNC16(bb + 18432u + (uint32_t)m * 9216u + (uint32_t)(k * 144 + s * 16), src);
            }
            CP_COMMIT();
        };

        float acc1[2][4][4] = {};
        float acc3[2][4][4] = {};

        uint32_t aoff = (uint32_t)(((lane & 15) + wy * 32) * 144 + (lane >> 4) * 16);
        uint32_t boff = 18432u + (uint32_t)((lane & 15) * 144 + ((lane >> 4) * 8 + wx * 32) * 2);

        load_chunk(0, 0);
        load_chunk(1, 1);

        for (int c = 0; c < NCHUNK; c++) {
            if (c < NCHUNK - 1) CP_WAIT1(); else CP_WAIT0();
            __syncthreads();
            if (c + 2 < NCHUNK) load_chunk(c + 2, (c + 2) % 3);

            uint32_t bb = sbase + (uint32_t)(c % 3) * G1_BUFB;
            #pragma unroll
            for (int ks = 0; ks < 4; ks++) {
                uint32_t af[2][4];
                LDSM4(af[0][0], af[0][1], af[0][2], af[0][3], bb + aoff + ks * 32);
                LDSM4(af[1][0], af[1][1], af[1][2], af[1][3], bb + aoff + 2304 + ks * 32);
                uint32_t b1f[8], b3f[8];
                LDSM4T(b1f[0], b1f[1], b1f[2], b1f[3], bb + boff + ks * 2304);
                LDSM4T(b1f[4], b1f[5], b1f[6], b1f[7], bb + boff + ks * 2304 + 32);
                LDSM4T(b3f[0], b3f[1], b3f[2], b3f[3], bb + boff + 9216 + ks * 2304);
                LDSM4T(b3f[4], b3f[5], b3f[6], b3f[7], bb + boff + 9216 + ks * 2304 + 32);
                #pragma unroll
                for (int mt = 0; mt < 2; mt++)
                    #pragma unroll
                    for (int nt = 0; nt < 4; nt++) {
                        MMA_F16(acc1[mt][nt], af[mt], b1f[2 * nt], b1f[2 * nt + 1]);
                        MMA_F16(acc3[mt][nt], af[mt], b3f[2 * nt], b3f[2 * nt + 1]);
                    }
            }
        }

        // Epilogue: SwiGLU -> half2 -> g_h
        int rbase = row0 + wy * 32 + (lane >> 2);
        int cbase = col0 + wx * 32 + 2 * (lane & 3);
        #pragma unroll
        for (int mt = 0; mt < 2; mt++)
            #pragma unroll
            for (int nt = 0; nt < 4; nt++) {
                int col = cbase + nt * 8;
                #pragma unroll
                for (int h = 0; h < 2; h++) {
                    int r = rbase + mt * 16 + h * 8;
                    float a0 = acc1[mt][nt][2 * h], a1 = acc1[mt][nt][2 * h + 1];
                    float s0 = a0 / (1.f + __expf(-a0));
                    float s1 = a1 / (1.f + __expf(-a1));
                    *reinterpret_cast<__half2*>(g_h + (size_t)r * DH + col) =
                        __floats2half2_rn(s0 * acc3[mt][nt][2 * h], s1 * acc3[mt][nt][2 * h + 1]);
                }
            }
    }
    // Publish completion (also for padding tiles so gemm2 gating saturates).
    __syncthreads();
    if (tid == 0) {
        __threadfence();
        atomicAdd(&g_done1[y], 1);
    }
}

__device__ __forceinline__ void gemm2_tile(unsigned char* dsm, int y, int x,
                                           int tid, int lane, int wy, int wx) {
    int e = g_tile_e[y];
    if (e < 0) return;
    // Gate on all 16 gemm1 x-tiles of this row block.
    if (tid == 0) {
        while (atomicAdd(&g_done1[y], 0) < 16) __nanosleep(64);
    }
    __syncthreads();
    __threadfence();

    const __half* W2 = g_w2h + (size_t)e * DH * DM;
    int row0 = y * 128;
    int col0 = x * 128;
    uint32_t sbase = smem_u32(dsm);

    auto load_chunk = [&](int c, int b) {
        int k0 = c * KC;
        uint32_t bb = sbase + (uint32_t)b * G2_BUFB;
        #pragma unroll
        for (int i = 0; i < 4; i++) {               // A
            int idx = tid + i * 256;
            int r = idx >> 3, s = idx & 7;
            CP_ASYNC16(bb + (uint32_t)(r * 144 + s * 16),
                       g_h + (size_t)(row0 + r) * DH + k0 + s * 8);
        }
        #pragma unroll
        for (int i = 0; i < 4; i++) {               // B: 64 rows x 16 segs
            int idx = tid + i * 256;
            int k = idx >> 4, s = idx & 15;
            CP_ASYNC16(bb + 18432u + (uint32_t)(k * 272 + s * 16),
                       W2 + (size_t)(k0 + k) * DM + col0 + s * 8);
        }
        CP_COMMIT();
    };

    float acc[2][8][4] = {};

    uint32_t aoff = (uint32_t)(((lane & 15) + wy * 32) * 144 + (lane >> 4) * 16);
    uint32_t boff = 18432u + (uint32_t)((lane & 15) * 272 + ((lane >> 4) * 8 + wx * 64) * 2);

    load_chunk(0, 0);
    load_chunk(1, 1);

    for (int c = 0; c < NCHUNK; c++) {
        if (c < NCHUNK - 1) CP_WAIT1(); else CP_WAIT0();
        __syncthreads();
        if (c + 2 < NCHUNK) load_chunk(c + 2, (c + 2) % 3);

        uint32_t bb = sbase + (uint32_t)(c % 3) * G2_BUFB;
        #pragma unroll
        for (int ks = 0; ks < 4; ks++) {
            uint32_t af[2][4];
            LDSM4(af[0][0], af[0][1], af[0][2], af[0][3], bb + aoff + ks * 32);
            LDSM4(af[1][0], af[1][1], af[1][2], af[1][3], bb + aoff + 2304 + ks * 32);
            uint32_t bf[16];
            #pragma unroll
            for (int q = 0; q < 4; q++)
                LDSM4T(bf[4 * q], bf[4 * q + 1], bf[4 * q + 2], bf[4 * q + 3],
                       bb + boff + ks * 4352 + q * 32);
            #pragma unroll
            for (int mt = 0; mt < 2; mt++)
                #pragma unroll
                for (int nt = 0; nt < 8; nt++)
                    MMA_F16(acc[mt][nt], af[mt], bf[2 * nt], bf[2 * nt + 1]);
        }
    }

    int rbase = row0 + wy * 32 + (lane >> 2);
    int cbase = col0 + wx * 64 + 2 * (lane & 3);
    #pragma unroll
    for (int mt = 0; mt < 2; mt++)
        #pragma unroll
        for (int nt = 0; nt < 8; nt++) {
            int col = cbase + nt * 8;
            #pragma unroll
            for (int h = 0; h < 2; h++) {
                int r = rbase + mt * 16 + h * 8;
                float2 o;
                o.x = acc[mt][nt][2 * h];
                o.y = acc[mt][nt][2 * h + 1];
                *reinterpret_cast<float2*>(g_op + (size_t)r * DM + col) = o;
            }
        }
}

// ---------------------------------------------------------------------------
// Persistent fused GEMM kernel: work-stealing over T1+T2 tiles.
// ---------------------------------------------------------------------------
__global__ __launch_bounds__(256, 2)
void k_moe_gemms() {
    extern __shared__ __align__(16) unsigned char dsm[];
    __shared__ int s_tile;

    int tid  = threadIdx.x;
    int lane = tid & 31;
    int wid  = tid >> 5;
    int wy   = wid >> 1;
    int wx   = wid & 1;

    for (;;) {
        if (tid == 0) s_tile = atomicAdd(&g_tilectr, 1);
        __syncthreads();
        int t = s_tile;
        __syncthreads();
        if (t >= T1 + T2) break;
        if (t < T1) {
            gemm1_tile(dsm, t >> 4, t & 15, tid, lane, wy, wx);
        } else {
            int u = t - T1;
            gemm2_tile(dsm, u >> 3, u & 7, tid, lane, wy, wx);
        }
        __syncthreads();
    }
}

// ---------------------------------------------------------------------------
__global__ void k_combine(const float* __restrict__ ew, float* __restrict__ out) {
    int n = blockIdx.x;
    int c = threadIdx.x;
    float wa = ew[n * TOPK + 0];
    float wb = ew[n * TOPK + 1];
    int pa = g_pos[n * TOPK + 0];
    int pb = g_pos[n * TOPK + 1];
    float4 a = reinterpret_cast<const float4*>(g_op + (size_t)pa * DM)[c];
    float4 b = reinterpret_cast<const float4*>(g_op + (size_t)pb * DM)[c];
    float4 o;
    o.x = wa * a.x + wb * b.x;
    o.y = wa * a.y + wb * b.y;
    o.z = wa * a.z + wb * b.z;
    o.w = wa * a.w + wb * b.w;
    reinterpret_cast<float4*>(out + (size_t)n * DM)[c] = o;
}

// ---------------------------------------------------------------------------
extern "C" void kernel_launch(void* const* d_in, const int* in_sizes, int n_in,
                              void* d_out, int out_size) {
    const float* x    = (const float*)d_in[0];
    const float* ew   = (const float*)d_in[1];
    const int*   idx  = (const int*)  d_in[2];
    const int*   bspe = (const int*)  d_in[3];
    const float* w1   = (const float*)d_in[4];
    const float* w2   = (const float*)d_in[5];
    const float* w3   = (const float*)d_in[6];
    float* out = (float*)d_out;

    static cudaStream_t s2 = nullptr;
    static cudaEvent_t evStart = nullptr, evW = nullptr;
    if (!s2) {
        cudaStreamCreateWithFlags(&s2, cudaStreamNonBlocking);
        cudaEventCreateWithFlags(&evStart, cudaEventDisableTiming);
        cudaEventCreateWithFlags(&evW, cudaEventDisableTiming);
        cudaFuncSetAttribute(k_moe_gemms, cudaFuncAttributeMaxDynamicSharedMemorySize, P_DYN);
    }

    // Fork: weight conversion on s2 overlaps permute pipeline on main stream.
    cudaEventRecord(evStart, 0);
    cudaStreamWaitEvent(s2, evStart, 0);
    k_cvtw13<<<dim3(WELEMS / 4 / 256, 2), 256, 0, s2>>>(w1, w3);
    k_cvtw2<<<WELEMS / 4 / 256, 256, 0, s2>>>(w2);
    cudaEventRecord(evW, s2);

    k_setup<<<1, 32>>>(bspe);
    k_scatter<<<NK / 256, 256>>>(idx);
    k_gather<<<MAXROWS, 256>>>(x, bspe);

    cudaStreamWaitEvent(0, evW, 0);
    k_moe_gemms<<<PERSIST, 256, P_DYN>>>();

    k_combine<<<N_TOK, 256>>>(ew, out);
}